// round 3
// baseline (speedup 1.0000x reference)
#include <cuda_runtime.h>
#include <math.h>

#define TT 500
#define NN 21
#define BB 64
#define THREADS 512
#define HSTRIDE 130   // float2 units per H row (128 used + 2 pad, breaks bank alignment)

// ---------------- device scratch ----------------
__device__ __align__(16) float g_A[NN * NN];        // A[n][j]
__device__ __align__(16) float g_W1zr[256 * 128];   // [c][k]
__device__ __align__(16) float g_W1h[128 * 128];
__device__ __align__(16) float g_W2g[384 * 128];    // Mz|Mr|Mh
__device__ __align__(16) float g_W2zr[256 * 128];
__device__ __align__(16) float g_W2h[128 * 128];
__device__ __align__(16) float g_c1[6 * 128];       // uz,ur,uh,cz,cr,ch
__device__ __align__(16) float g_c2[3 * 128];       // dz,dr,dh

// ---------------- smem ----------------
struct SM {
  float2 YP[TT * 11];        // [t*11+p] : (A@x_t) pair-major, pad .y of p=10 is 0
  float2 AP[11 * 22];        // [p*22+j] : (A[2p][j], A[2p+1][j]); j=21 & row 21 are 0
  float2 H1P[11 * HSTRIDE];  // pair-major H: [p][k]
  float2 H2P[11 * HSTRIDE];
  float2 XP[11 * HSTRIDE];   // scratch: H*R then A@H1 then H2*R2
  float2 ZC[128 * 11];       // [c*11+p] z-gate
  float2 GC[384 * 11];       // layer-2 gcn pre-acts
  float uz[128], ur[128], uh[128], cz[128], cr[128], ch[128];
  float dz[128], dr[128], dh[128];
  float clsw[128];
  float red[16];
};

// ---------------- helpers ----------------
__device__ __forceinline__ float2 ffma2(float2 a, float2 b, float2 c) {
  float2 d;
  asm("fma.rn.f32x2 %0, %1, %2, %3;"
      : "=l"(reinterpret_cast<unsigned long long&>(d))
      : "l"(reinterpret_cast<unsigned long long&>(a)),
        "l"(reinterpret_cast<unsigned long long&>(b)),
        "l"(reinterpret_cast<unsigned long long&>(c)));
  return d;
}

__device__ __forceinline__ float sigm(float v) {
  return 1.0f / (1.0f + __expf(-v));
}
__device__ __forceinline__ float ftanh(float x) {
  x = fminf(fmaxf(x, -15.f), 15.f);
  float e = __expf(2.0f * x);
  return __fdividef(e - 1.0f, e + 1.0f);
}

// acc[pp] += sum_k HP[p0+pp][k] * w[k]   (H pair-major, w streamed via LDG.128)
template <int NP>
__device__ __forceinline__ void taskdot(const float2* __restrict__ hp,
                                        const float* __restrict__ w,
                                        float2* acc) {
#pragma unroll 2
  for (int k = 0; k < 128; k += 4) {
    const float4 w4 = __ldg(reinterpret_cast<const float4*>(w + k));
#pragma unroll
    for (int pp = 0; pp < NP; pp++) {
      const float4 hA = *reinterpret_cast<const float4*>(hp + pp * HSTRIDE + k);
      const float4 hB = *reinterpret_cast<const float4*>(hp + pp * HSTRIDE + k + 2);
      acc[pp] = ffma2(make_float2(hA.x, hA.y), make_float2(w4.x, w4.x), acc[pp]);
      acc[pp] = ffma2(make_float2(hA.z, hA.w), make_float2(w4.y, w4.y), acc[pp]);
      acc[pp] = ffma2(make_float2(hB.x, hB.y), make_float2(w4.z, w4.z), acc[pp]);
      acc[pp] = ffma2(make_float2(hB.z, hB.w), make_float2(w4.w, w4.w), acc[pp]);
    }
  }
}

// ---------------- prep ----------------
__global__ void prep_A_kernel(const int* __restrict__ ei,
                              const float* __restrict__ ew, int E) {
  if (threadIdx.x != 0 || blockIdx.x != 0) return;
  float deg[NN], dinv[NN];
  for (int n = 0; n < NN; n++) deg[n] = 1.0f;
  for (int e = 0; e < E; e++) deg[ei[E + e]] += ew[e];
  for (int n = 0; n < NN; n++) dinv[n] = (deg[n] > 0.f) ? rsqrtf(deg[n]) : 0.f;
  for (int i = 0; i < NN * NN; i++) g_A[i] = 0.f;
  for (int e = 0; e < E; e++) {
    int s = ei[e], d = ei[E + e];
    g_A[d * NN + s] += dinv[s] * ew[e] * dinv[d];
  }
  for (int n = 0; n < NN; n++) g_A[n * NN + n] += dinv[n] * dinv[n];
}

__global__ void prep_W_kernel(
    const float* Wz1, const float* bz1, const float* lzw1, const float* lzb1,
    const float* Wr1, const float* br1, const float* lrw1, const float* lrb1,
    const float* Wh1, const float* bh1, const float* lhw1, const float* lhb1,
    const float* Wz2, const float* bz2, const float* lzw2, const float* lzb2,
    const float* Wr2, const float* br2, const float* lrw2, const float* lrb2,
    const float* Wh2, const float* bh2, const float* lhw2, const float* lhb2) {
  int t0 = blockIdx.x * blockDim.x + threadIdx.x;
  int nt = gridDim.x * blockDim.x;
  for (int i = t0; i < 256 * 128; i += nt) {
    int c = i >> 7, k = i & 127;
    g_W1zr[i] = (c < 128) ? lzw1[(128 + k) * 128 + c]
                          : lrw1[(128 + k) * 128 + (c - 128)];
    g_W2zr[i] = (c < 128) ? lzw2[(128 + k) * 128 + c]
                          : lrw2[(128 + k) * 128 + (c - 128)];
  }
  for (int i = t0; i < 128 * 128; i += nt) {
    int c = i >> 7, k = i & 127;
    g_W1h[i] = lhw1[(128 + k) * 128 + c];
    g_W2h[i] = lhw2[(128 + k) * 128 + c];
  }
  for (int i = t0; i < 384 * 128; i += nt) {
    int c = i >> 7, k = i & 127;
    const float *W, *lw;
    int cc = c;
    if (c < 128) { W = Wz2; lw = lzw2; }
    else if (c < 256) { W = Wr2; lw = lrw2; cc = c - 128; }
    else { W = Wh2; lw = lhw2; cc = c - 256; }
    float s = 0.f;
    for (int m = 0; m < 128; m++) s += W[k * 128 + m] * lw[m * 128 + cc];
    g_W2g[i] = s;
  }
  for (int c = t0; c < 128; c += nt) {
    float uz = 0, ur = 0, uh = 0, cz = 0, cr = 0, ch = 0, dz = 0, dr = 0, dh = 0;
    for (int m = 0; m < 128; m++) {
      uz += Wz1[m] * lzw1[m * 128 + c];
      ur += Wr1[m] * lrw1[m * 128 + c];
      uh += Wh1[m] * lhw1[m * 128 + c];
      cz += bz1[m] * lzw1[m * 128 + c];
      cr += br1[m] * lrw1[m * 128 + c];
      ch += bh1[m] * lhw1[m * 128 + c];
      dz += bz2[m] * lzw2[m * 128 + c];
      dr += br2[m] * lrw2[m * 128 + c];
      dh += bh2[m] * lhw2[m * 128 + c];
    }
    g_c1[0 * 128 + c] = uz;
    g_c1[1 * 128 + c] = ur;
    g_c1[2 * 128 + c] = uh;
    g_c1[3 * 128 + c] = cz + lzb1[c];
    g_c1[4 * 128 + c] = cr + lrb1[c];
    g_c1[5 * 128 + c] = ch + lhb1[c];
    g_c2[0 * 128 + c] = dz + lzb2[c];
    g_c2[1 * 128 + c] = dr + lrb2[c];
    g_c2[2 * 128 + c] = dh + lhb2[c];
  }
}

// ---------------- per-pass activation helpers ----------------
// pass1/pass5 (z/r gates, layer sel by pointers)
template <int NP>
__device__ __forceinline__ void act_zr1(SM* s, float2* acc, int p0, int cf,
                                        bool isZ, float u, float cc, int t) {
#pragma unroll
  for (int pp = 0; pp < NP; pp++) {
    int p = p0 + pp;
    float2 y = s->YP[t * 11 + p];
    float vx = sigm(acc[pp].x + y.x * u + cc);
    float vy = sigm(acc[pp].y + y.y * u + cc);
    if (isZ) {
      s->ZC[cf * 11 + p] = make_float2(vx, vy);
    } else {
      float2 h = s->H1P[p * HSTRIDE + cf];
      s->XP[p * HSTRIDE + cf] = make_float2(h.x * vx, h.y * vy);
    }
  }
}

template <int NP>
__device__ __forceinline__ void act_zr2(SM* s, float2* acc, int p0, int cf,
                                        bool isZ, int c) {
#pragma unroll
  for (int pp = 0; pp < NP; pp++) {
    int p = p0 + pp;
    float2 g = s->GC[c * 11 + p];
    float vx = sigm(acc[pp].x + g.x);
    float vy = sigm(acc[pp].y + g.y);
    if (isZ) {
      s->ZC[cf * 11 + p] = make_float2(vx, vy);
    } else {
      float2 h = s->H2P[p * HSTRIDE + cf];
      s->XP[p * HSTRIDE + cf] = make_float2(h.x * vx, h.y * vy);
    }
  }
}

template <int NP>
__device__ __forceinline__ void act_h1(SM* s, float2* acc, int p0, int c,
                                       float u, float cc, int t) {
#pragma unroll
  for (int pp = 0; pp < NP; pp++) {
    int p = p0 + pp;
    float2 y = s->YP[t * 11 + p];
    float hx = ftanh(acc[pp].x + y.x * u + cc);
    float hy = ftanh(acc[pp].y + y.y * u + cc);
    float2 z = s->ZC[c * 11 + p];
    float2 h = s->H1P[p * HSTRIDE + c];
    s->H1P[p * HSTRIDE + c] =
        make_float2(z.x * h.x + (1.f - z.x) * hx, z.y * h.y + (1.f - z.y) * hy);
  }
}

template <int NP>
__device__ __forceinline__ float act_h2(SM* s, float2* acc, int p0, int c) {
  float os = 0.f;
#pragma unroll
  for (int pp = 0; pp < NP; pp++) {
    int p = p0 + pp;
    float2 g = s->GC[(256 + c) * 11 + p];
    float hx = ftanh(acc[pp].x + g.x);
    float hy = ftanh(acc[pp].y + g.y);
    float2 z = s->ZC[c * 11 + p];
    float2 h = s->H2P[p * HSTRIDE + c];
    float nx = z.x * h.x + (1.f - z.x) * hx;
    float ny = z.y * h.y + (1.f - z.y) * hy;
    s->H2P[p * HSTRIDE + c] = make_float2(nx, ny);
    os += nx + ((p == 10) ? 0.f : ny);  // node 21 is padding
  }
  return os;
}

// ---------------- main kernel: 1 CTA per batch, 512 threads ----------------
__global__ void __launch_bounds__(THREADS, 1)
tgcn_main(const float* __restrict__ x, const float* __restrict__ clsw,
          const float* __restrict__ clsb, float* __restrict__ out) {
  extern __shared__ __align__(16) unsigned char smraw[];
  SM* s = reinterpret_cast<SM*>(smraw);
  const int tid = threadIdx.x;
  const int b = blockIdx.x;

  // ---- consts into smem ----
  for (int i = tid; i < 128; i += THREADS) {
    s->uz[i] = g_c1[i];
    s->ur[i] = g_c1[128 + i];
    s->uh[i] = g_c1[256 + i];
    s->cz[i] = g_c1[384 + i];
    s->cr[i] = g_c1[512 + i];
    s->ch[i] = g_c1[640 + i];
    s->dz[i] = g_c2[i];
    s->dr[i] = g_c2[128 + i];
    s->dh[i] = g_c2[256 + i];
    s->clsw[i] = clsw[i];
  }
  for (int i = tid; i < 11 * HSTRIDE; i += THREADS) {
    s->H1P[i] = make_float2(0.f, 0.f);
    s->H2P[i] = make_float2(0.f, 0.f);
    s->XP[i] = make_float2(0.f, 0.f);
  }
  // AP: pair-major A, zero-padded beyond node 20
  for (int i = tid; i < 11 * 22; i += THREADS) {
    int p = i / 22, j = i - 22 * p;
    float ax = 0.f, ay = 0.f;
    if (j < NN) {
      ax = g_A[(2 * p) * NN + j];
      if (2 * p + 1 < NN) ay = g_A[(2 * p + 1) * NN + j];
    }
    s->AP[i] = make_float2(ax, ay);
  }
  __syncthreads();

  // ---- precompute YP[t][p] = pair-major (A @ x_t), all steps ----
  const float* xb = x + (size_t)b * TT * NN;
  for (int i = tid; i < TT * 11; i += THREADS) {
    int t = i / 11, p = i - 11 * t;
    float2 acc = make_float2(0.f, 0.f);
    const float2* ap = s->AP + p * 22;
#pragma unroll
    for (int j = 0; j < NN; j++) {
      float xv = __ldg(xb + t * NN + j);
      acc = ffma2(ap[j], make_float2(xv, xv), acc);
    }
    s->YP[i] = acc;
  }
  __syncthreads();

  float osum_total = 0.f;

  for (int t = 0; t < TT; t++) {
    // ---- pass 1: layer1 Z & R (C=256, 1024 tasks, 2/thread) ----
#pragma unroll
    for (int i = 0; i < 2; i++) {
      const int task = tid + i * THREADS;
      const int c = task & 255;
      const int q = task >> 8;
      const int p0 = 3 * q;
      const int cf = c & 127;
      const bool isZ = (c < 128);
      const float u = isZ ? s->uz[cf] : s->ur[cf];
      const float cc = isZ ? s->cz[cf] : s->cr[cf];
      const float* wrow = g_W1zr + c * 128;
      const float2* hp = s->H1P + p0 * HSTRIDE;
      if (q < 3) {
        float2 acc[3] = {{0, 0}, {0, 0}, {0, 0}};
        taskdot<3>(hp, wrow, acc);
        act_zr1<3>(s, acc, p0, cf, isZ, u, cc, t);
      } else {
        float2 acc[2] = {{0, 0}, {0, 0}};
        taskdot<2>(hp, wrow, acc);
        act_zr1<2>(s, acc, p0, cf, isZ, u, cc, t);
      }
    }
    __syncthreads();

    // ---- pass 2: layer1 h-gate + H1 update (C=128, 512 tasks) ----
    {
      const int c = tid & 127;
      const int q = tid >> 7;
      const int p0 = 3 * q;
      const float u = s->uh[c], cc = s->ch[c];
      const float* wrow = g_W1h + c * 128;
      const float2* hp = s->XP + p0 * HSTRIDE;
      if (q < 3) {
        float2 acc[3] = {{0, 0}, {0, 0}, {0, 0}};
        taskdot<3>(hp, wrow, acc);
        act_h1<3>(s, acc, p0, c, u, cc, t);
      } else {
        float2 acc[2] = {{0, 0}, {0, 0}};
        taskdot<2>(hp, wrow, acc);
        act_h1<2>(s, acc, p0, c, u, cc, t);
      }
    }
    __syncthreads();

    // ---- pass 3: node mix  XP[p][k] = sum_j AP[p][j] * H1[j][k] ----
    {
      const int k = tid >> 2;
      const int q = tid & 3;
      const int p0 = 3 * q;
      const int np = (q < 3) ? 3 : 2;
      float2 hcol[11];
#pragma unroll
      for (int j2 = 0; j2 < 11; j2++) hcol[j2] = s->H1P[j2 * HSTRIDE + k];
      for (int pp = 0; pp < np; pp++) {
        int p = p0 + pp;
        const float2* ap = s->AP + p * 22;
        float2 a = make_float2(0.f, 0.f);
#pragma unroll
        for (int j = 0; j < NN; j++) {
          float hj = (j & 1) ? hcol[j >> 1].y : hcol[j >> 1].x;
          a = ffma2(ap[j], make_float2(hj, hj), a);
        }
        s->XP[p * HSTRIDE + k] = a;
      }
    }
    __syncthreads();

    // ---- pass 4: layer2 gcn pre-acts (C=384, 1536 tasks, 3/thread) ----
#pragma unroll
    for (int i = 0; i < 3; i++) {
      const int task = tid + i * THREADS;
      const int q = task / 384;
      const int c = task - q * 384;
      const int p0 = 3 * q;
      const float dterm =
          (c < 128) ? s->dz[c] : (c < 256) ? s->dr[c - 128] : s->dh[c - 256];
      const float* wrow = g_W2g + c * 128;
      const float2* hp = s->XP + p0 * HSTRIDE;
      if (q < 3) {
        float2 acc[3] = {{0, 0}, {0, 0}, {0, 0}};
        taskdot<3>(hp, wrow, acc);
#pragma unroll
        for (int pp = 0; pp < 3; pp++)
          s->GC[c * 11 + p0 + pp] =
              make_float2(acc[pp].x + dterm, acc[pp].y + dterm);
      } else {
        float2 acc[2] = {{0, 0}, {0, 0}};
        taskdot<2>(hp, wrow, acc);
#pragma unroll
        for (int pp = 0; pp < 2; pp++)
          s->GC[c * 11 + p0 + pp] =
              make_float2(acc[pp].x + dterm, acc[pp].y + dterm);
      }
    }
    __syncthreads();

    // ---- pass 5: layer2 Z & R (C=256, 1024 tasks, 2/thread) ----
#pragma unroll
    for (int i = 0; i < 2; i++) {
      const int task = tid + i * THREADS;
      const int c = task & 255;
      const int q = task >> 8;
      const int p0 = 3 * q;
      const int cf = c & 127;
      const bool isZ = (c < 128);
      const float* wrow = g_W2zr + c * 128;
      const float2* hp = s->H2P + p0 * HSTRIDE;
      if (q < 3) {
        float2 acc[3] = {{0, 0}, {0, 0}, {0, 0}};
        taskdot<3>(hp, wrow, acc);
        act_zr2<3>(s, acc, p0, cf, isZ, c);
      } else {
        float2 acc[2] = {{0, 0}, {0, 0}};
        taskdot<2>(hp, wrow, acc);
        act_zr2<2>(s, acc, p0, cf, isZ, c);
      }
    }
    __syncthreads();

    // ---- pass 6: layer2 h-gate + H2 update + output accum ----
    {
      const int c = tid & 127;
      const int q = tid >> 7;
      const int p0 = 3 * q;
      const float* wrow = g_W2h + c * 128;
      const float2* hp = s->XP + p0 * HSTRIDE;
      if (q < 3) {
        float2 acc[3] = {{0, 0}, {0, 0}, {0, 0}};
        taskdot<3>(hp, wrow, acc);
        osum_total += act_h2<3>(s, acc, p0, c);
      } else {
        float2 acc[2] = {{0, 0}, {0, 0}};
        taskdot<2>(hp, wrow, acc);
        osum_total += act_h2<2>(s, acc, p0, c);
      }
    }
    __syncthreads();
  }

  // ---- final reduction ----
  float v = osum_total * s->clsw[tid & 127];
#pragma unroll
  for (int off = 16; off > 0; off >>= 1)
    v += __shfl_down_sync(0xffffffffu, v, off);
  if ((tid & 31) == 0) s->red[tid >> 5] = v;
  __syncthreads();
  if (tid == 0) {
    float tot = 0.f;
#pragma unroll
    for (int w = 0; w < 16; w++) tot += s->red[w];
    out[b] = tot * (1.0f / (TT * NN)) + clsb[0];
  }
}

// ---------------- launch ----------------
extern "C" void kernel_launch(void* const* d_in, const int* in_sizes, int n_in,
                              void* d_out, int out_size) {
  const float* x = (const float*)d_in[0];
  const int* ei = (const int*)d_in[1];
  const float* ew = (const float*)d_in[2];
  const float* Wz1 = (const float*)d_in[3];
  const float* bz1 = (const float*)d_in[4];
  const float* lzw1 = (const float*)d_in[5];
  const float* lzb1 = (const float*)d_in[6];
  const float* Wr1 = (const float*)d_in[7];
  const float* br1 = (const float*)d_in[8];
  const float* lrw1 = (const float*)d_in[9];
  const float* lrb1 = (const float*)d_in[10];
  const float* Wh1 = (const float*)d_in[11];
  const float* bh1 = (const float*)d_in[12];
  const float* lhw1 = (const float*)d_in[13];
  const float* lhb1 = (const float*)d_in[14];
  const float* Wz2 = (const float*)d_in[15];
  const float* bz2 = (const float*)d_in[16];
  const float* lzw2 = (const float*)d_in[17];
  const float* lzb2 = (const float*)d_in[18];
  const float* Wr2 = (const float*)d_in[19];
  const float* br2 = (const float*)d_in[20];
  const float* lrw2 = (const float*)d_in[21];
  const float* lrb2 = (const float*)d_in[22];
  const float* Wh2 = (const float*)d_in[23];
  const float* bh2 = (const float*)d_in[24];
  const float* lhw2 = (const float*)d_in[25];
  const float* lhb2 = (const float*)d_in[26];
  const float* clsw = (const float*)d_in[27];
  const float* clsb = (const float*)d_in[28];
  int E = in_sizes[1] / 2;

  prep_A_kernel<<<1, 32>>>(ei, ew, E);
  prep_W_kernel<<<128, 256>>>(Wz1, bz1, lzw1, lzb1, Wr1, br1, lrw1, lrb1, Wh1,
                              bh1, lhw1, lhb1, Wz2, bz2, lzw2, lzb2, Wr2, br2,
                              lrw2, lrb2, Wh2, bh2, lhw2, lhb2);

  cudaFuncSetAttribute(tgcn_main, cudaFuncAttributeMaxDynamicSharedMemorySize,
                       (int)sizeof(SM));
  tgcn_main<<<BB, THREADS, sizeof(SM)>>>(x, clsw, clsb, (float*)d_out);
}

// round 4
// speedup vs baseline: 3.0032x; 3.0032x over previous
#include <cuda_runtime.h>
#include <math.h>

#define TT 500
#define NN 21
#define BB 64
#define THREADS 256
#define HROW 28  // floats per H row (22 used, padded to 112B: 16B-aligned, k-stride)

// ---------------- device scratch (c-major weight layouts) ----------------
__device__ __align__(16) float g_A[NN * NN];
__device__ __align__(16) float g_W1zr[128 * 256];  // [k][c] c<128: z, else r (bottom half of l*w1)
__device__ __align__(16) float g_W1h[128 * 128];   // [k][c]
__device__ __align__(16) float g_W2g[128 * 384];   // [k][c] Mz|Mr|Mh  (M = W2 @ lw2_top)
__device__ __align__(16) float g_W2zr[128 * 256];  // [k][c]
__device__ __align__(16) float g_W2h[128 * 128];   // [k][c]
__device__ __align__(16) float g_c1[6 * 128];      // uz,ur,uh,czb,crb,chb
__device__ __align__(16) float g_c2[3 * 128];      // dzb,drb,dhb

// ---------------- smem ----------------
struct SM {
  float2 YP[TT * 11];   // pair-major A@x_t, .y of p=10 is 0
  float2 AP[11 * 22];   // AP[p][j] = (A[2p][j], A[2p+1][j]); j=21 / row21 = 0
  float H1[128 * HROW]; // H1[k][node]
  float H2[128 * HROW];
  float XP[128 * HROW]; // scratch: H1*R -> A@H1'
  float XR2[128 * HROW];
  float ZC[128 * 24];   // z-gate [c][node]
  float uz[128], ur[128], uh[128], czb[128], crb[128], chb[128];
  float dzb[128], drb[128], dhb[128];
  float clsw[128];
  float red[8];
};

// ---------------- helpers ----------------
__device__ __forceinline__ float2 ffma2(float2 a, float2 b, float2 c) {
  float2 d;
  asm("fma.rn.f32x2 %0, %1, %2, %3;"
      : "=l"(reinterpret_cast<unsigned long long&>(d))
      : "l"(reinterpret_cast<unsigned long long&>(a)),
        "l"(reinterpret_cast<unsigned long long&>(b)),
        "l"(reinterpret_cast<unsigned long long&>(c)));
  return d;
}
__device__ __forceinline__ float tanha(float x) {
  float y;
  asm("tanh.approx.f32 %0, %1;" : "=f"(y) : "f"(x));
  return y;
}
__device__ __forceinline__ float sigma(float x) {
  return fmaf(tanha(0.5f * x), 0.5f, 0.5f);
}

// load node-pairs of one H row. HALF=0: pairs 0-5 (floats 0..11); HALF=1: pairs 6-10 (12..21)
template <int HALF>
__device__ __forceinline__ void ldrow(const float* __restrict__ r, float2* v) {
  if (HALF == 0) {
    float4 a = *reinterpret_cast<const float4*>(r);
    float4 b = *reinterpret_cast<const float4*>(r + 4);
    float4 c = *reinterpret_cast<const float4*>(r + 8);
    v[0] = make_float2(a.x, a.y); v[1] = make_float2(a.z, a.w);
    v[2] = make_float2(b.x, b.y); v[3] = make_float2(b.z, b.w);
    v[4] = make_float2(c.x, c.y); v[5] = make_float2(c.z, c.w);
  } else {
    float4 a = *reinterpret_cast<const float4*>(r + 12);
    float4 b = *reinterpret_cast<const float4*>(r + 16);
    float2 c = *reinterpret_cast<const float2*>(r + 20);
    v[0] = make_float2(a.x, a.y); v[1] = make_float2(a.z, a.w);
    v[2] = make_float2(b.x, b.y); v[3] = make_float2(b.z, b.w);
    v[4] = c;
  }
}

// ---------------- prep ----------------
__global__ void prep_A_kernel(const int* __restrict__ ei,
                              const float* __restrict__ ew, int E) {
  if (threadIdx.x != 0 || blockIdx.x != 0) return;
  float deg[NN], dinv[NN];
  for (int n = 0; n < NN; n++) deg[n] = 1.0f;
  for (int e = 0; e < E; e++) deg[ei[E + e]] += ew[e];
  for (int n = 0; n < NN; n++) dinv[n] = (deg[n] > 0.f) ? rsqrtf(deg[n]) : 0.f;
  for (int i = 0; i < NN * NN; i++) g_A[i] = 0.f;
  for (int e = 0; e < E; e++) {
    int s = ei[e], d = ei[E + e];
    g_A[d * NN + s] += dinv[s] * ew[e] * dinv[d];
  }
  for (int n = 0; n < NN; n++) g_A[n * NN + n] += dinv[n] * dinv[n];
}

__global__ void prep_W_kernel(
    const float* Wz1, const float* bz1, const float* lzw1, const float* lzb1,
    const float* Wr1, const float* br1, const float* lrw1, const float* lrb1,
    const float* Wh1, const float* bh1, const float* lhw1, const float* lhb1,
    const float* Wz2, const float* bz2, const float* lzw2, const float* lzb2,
    const float* Wr2, const float* br2, const float* lrw2, const float* lrb2,
    const float* Wh2, const float* bh2, const float* lhw2, const float* lhb2) {
  int t0 = blockIdx.x * blockDim.x + threadIdx.x;
  int nt = gridDim.x * blockDim.x;
  // c-major repacks: idx = k*C + c
  for (int i = t0; i < 128 * 256; i += nt) {
    int k = i >> 8, c = i & 255;
    g_W1zr[i] = (c < 128) ? lzw1[(128 + k) * 128 + c]
                          : lrw1[(128 + k) * 128 + (c - 128)];
    g_W2zr[i] = (c < 128) ? lzw2[(128 + k) * 128 + c]
                          : lrw2[(128 + k) * 128 + (c - 128)];
  }
  for (int i = t0; i < 128 * 128; i += nt) {
    int k = i >> 7, c = i & 127;
    g_W1h[i] = lhw1[(128 + k) * 128 + c];
    g_W2h[i] = lhw2[(128 + k) * 128 + c];
  }
  for (int i = t0; i < 128 * 384; i += nt) {
    int k = i / 384, c = i - k * 384;
    const float *W, *lw;
    int cc = c;
    if (c < 128) { W = Wz2; lw = lzw2; }
    else if (c < 256) { W = Wr2; lw = lrw2; cc = c - 128; }
    else { W = Wh2; lw = lhw2; cc = c - 256; }
    float s = 0.f;
    for (int m = 0; m < 128; m++) s += W[k * 128 + m] * lw[m * 128 + cc];
    g_W2g[i] = s;
  }
  for (int c = t0; c < 128; c += nt) {
    float uz = 0, ur = 0, uh = 0, cz = 0, cr = 0, ch = 0, dz = 0, dr = 0, dh = 0;
    for (int m = 0; m < 128; m++) {
      uz += Wz1[m] * lzw1[m * 128 + c];
      ur += Wr1[m] * lrw1[m * 128 + c];
      uh += Wh1[m] * lhw1[m * 128 + c];
      cz += bz1[m] * lzw1[m * 128 + c];
      cr += br1[m] * lrw1[m * 128 + c];
      ch += bh1[m] * lhw1[m * 128 + c];
      dz += bz2[m] * lzw2[m * 128 + c];
      dr += br2[m] * lrw2[m * 128 + c];
      dh += bh2[m] * lhw2[m * 128 + c];
    }
    g_c1[0 * 128 + c] = uz;
    g_c1[1 * 128 + c] = ur;
    g_c1[2 * 128 + c] = uh;
    g_c1[3 * 128 + c] = cz + lzb1[c];
    g_c1[4 * 128 + c] = cr + lrb1[c];
    g_c1[5 * 128 + c] = ch + lhb1[c];
    g_c2[0 * 128 + c] = dz + lzb2[c];
    g_c2[1 * 128 + c] = dr + lrb2[c];
    g_c2[2 * 128 + c] = dh + lhb2[c];
  }
}

// ---------------- per-step body (templated on node-half) ----------------
template <int HALF, int NP>
__device__ __forceinline__ float step_body(SM* s, int c, int t) {
  const int P0 = HALF ? 6 : 0;

  // ---- pass 1: layer1 z & r gates ----
  {
    float2 az[NP], ar[NP];
#pragma unroll
    for (int p = 0; p < NP; p++) az[p] = ar[p] = make_float2(0.f, 0.f);
    const float* wz = g_W1zr + c;
#pragma unroll 8
    for (int k = 0; k < 128; k++) {
      float vz = wz[k * 256];
      float vr = wz[k * 256 + 128];
      float2 hv[NP];
      ldrow<HALF>(s->H1 + k * HROW, hv);
      float2 z2 = make_float2(vz, vz), r2 = make_float2(vr, vr);
#pragma unroll
      for (int p = 0; p < NP; p++) {
        az[p] = ffma2(hv[p], z2, az[p]);
        ar[p] = ffma2(hv[p], r2, ar[p]);
      }
    }
    const float uzv = s->uz[c], czv = s->czb[c];
    const float urv = s->ur[c], crv = s->crb[c];
#pragma unroll
    for (int pp = 0; pp < NP; pp++) {
      int p = P0 + pp;
      float2 y = s->YP[t * 11 + p];
      float zx = sigma(az[pp].x + y.x * uzv + czv);
      float zy = sigma(az[pp].y + y.y * uzv + czv);
      float rx = sigma(ar[pp].x + y.x * urv + crv);
      float ry = sigma(ar[pp].y + y.y * urv + crv);
      *reinterpret_cast<float2*>(s->ZC + c * 24 + 2 * p) = make_float2(zx, zy);
      float2 h = *reinterpret_cast<float2*>(s->H1 + c * HROW + 2 * p);
      *reinterpret_cast<float2*>(s->XP + c * HROW + 2 * p) =
          make_float2(h.x * rx, h.y * ry);
    }
  }
  __syncthreads();

  // ---- pass 2: layer1 h-gate + H1 update ----
  {
    float2 ah[NP];
#pragma unroll
    for (int p = 0; p < NP; p++) ah[p] = make_float2(0.f, 0.f);
    const float* wh = g_W1h + c;
#pragma unroll 8
    for (int k = 0; k < 128; k++) {
      float vh = wh[k * 128];
      float2 hv[NP];
      ldrow<HALF>(s->XP + k * HROW, hv);
      float2 h2 = make_float2(vh, vh);
#pragma unroll
      for (int p = 0; p < NP; p++) ah[p] = ffma2(hv[p], h2, ah[p]);
    }
    const float uhv = s->uh[c], chv = s->chb[c];
#pragma unroll
    for (int pp = 0; pp < NP; pp++) {
      int p = P0 + pp;
      float2 y = s->YP[t * 11 + p];
      float hx = tanha(ah[pp].x + y.x * uhv + chv);
      float hy = tanha(ah[pp].y + y.y * uhv + chv);
      float2 z = *reinterpret_cast<float2*>(s->ZC + c * 24 + 2 * p);
      float2 h = *reinterpret_cast<float2*>(s->H1 + c * HROW + 2 * p);
      *reinterpret_cast<float2*>(s->H1 + c * HROW + 2 * p) = make_float2(
          z.x * h.x + (1.f - z.x) * hx, z.y * h.y + (1.f - z.y) * hy);
    }
  }
  __syncthreads();

  // ---- pass 3: node mix  XP[k][n] = sum_j A[n][j] * H1[k][j] ----
  {
    const int k = c;  // c == tid&127 doubles as the feature row here
    const float* hr = s->H1 + k * HROW;
    float hj[22];
#pragma unroll
    for (int q = 0; q < 5; q++) {
      float4 v = *reinterpret_cast<const float4*>(hr + 4 * q);
      hj[4 * q] = v.x; hj[4 * q + 1] = v.y; hj[4 * q + 2] = v.z; hj[4 * q + 3] = v.w;
    }
    {
      float2 v = *reinterpret_cast<const float2*>(hr + 20);
      hj[20] = v.x; hj[21] = v.y;
    }
#pragma unroll
    for (int pp = 0; pp < NP; pp++) {
      int p = P0 + pp;
      const float2* ap = s->AP + p * 22;
      float2 a = make_float2(0.f, 0.f);
#pragma unroll
      for (int j = 0; j < NN; j++) a = ffma2(ap[j], make_float2(hj[j], hj[j]), a);
      *reinterpret_cast<float2*>(s->XP + k * HROW + 2 * p) = a;
    }
  }
  __syncthreads();

  // ---- pass 4: layer2 z & r (fused gcn + hidden dots) ----
  {
    float2 az[NP], ar[NP];
#pragma unroll
    for (int p = 0; p < NP; p++) az[p] = ar[p] = make_float2(0.f, 0.f);
    const float* mg = g_W2g + c;
    const float* wz = g_W2zr + c;
#pragma unroll 4
    for (int k = 0; k < 128; k++) {
      float mz = mg[k * 384];
      float mr = mg[k * 384 + 128];
      float vz = wz[k * 256];
      float vr = wz[k * 256 + 128];
      float2 xv[NP], hv[NP];
      ldrow<HALF>(s->XP + k * HROW, xv);
      ldrow<HALF>(s->H2 + k * HROW, hv);
      float2 mz2 = make_float2(mz, mz), mr2 = make_float2(mr, mr);
      float2 vz2 = make_float2(vz, vz), vr2 = make_float2(vr, vr);
#pragma unroll
      for (int p = 0; p < NP; p++) {
        az[p] = ffma2(xv[p], mz2, az[p]);
        az[p] = ffma2(hv[p], vz2, az[p]);
        ar[p] = ffma2(xv[p], mr2, ar[p]);
        ar[p] = ffma2(hv[p], vr2, ar[p]);
      }
    }
    const float dzv = s->dzb[c], drv = s->drb[c];
#pragma unroll
    for (int pp = 0; pp < NP; pp++) {
      int p = P0 + pp;
      float zx = sigma(az[pp].x + dzv);
      float zy = sigma(az[pp].y + dzv);
      float rx = sigma(ar[pp].x + drv);
      float ry = sigma(ar[pp].y + drv);
      *reinterpret_cast<float2*>(s->ZC + c * 24 + 2 * p) = make_float2(zx, zy);
      float2 h = *reinterpret_cast<float2*>(s->H2 + c * HROW + 2 * p);
      *reinterpret_cast<float2*>(s->XR2 + c * HROW + 2 * p) =
          make_float2(h.x * rx, h.y * ry);
    }
  }
  __syncthreads();

  // ---- pass 5: layer2 h-gate + H2 update + output accum ----
  float osum = 0.f;
  {
    float2 ah[NP];
#pragma unroll
    for (int p = 0; p < NP; p++) ah[p] = make_float2(0.f, 0.f);
    const float* mh = g_W2g + 256 + c;
    const float* wh = g_W2h + c;
#pragma unroll 4
    for (int k = 0; k < 128; k++) {
      float mv = mh[k * 384];
      float wv = wh[k * 128];
      float2 xv[NP], rv[NP];
      ldrow<HALF>(s->XP + k * HROW, xv);
      ldrow<HALF>(s->XR2 + k * HROW, rv);
      float2 m2 = make_float2(mv, mv), w2 = make_float2(wv, wv);
#pragma unroll
      for (int p = 0; p < NP; p++) {
        ah[p] = ffma2(xv[p], m2, ah[p]);
        ah[p] = ffma2(rv[p], w2, ah[p]);
      }
    }
    const float dhv = s->dhb[c];
#pragma unroll
    for (int pp = 0; pp < NP; pp++) {
      int p = P0 + pp;
      float hx = tanha(ah[pp].x + dhv);
      float hy = tanha(ah[pp].y + dhv);
      float2 z = *reinterpret_cast<float2*>(s->ZC + c * 24 + 2 * p);
      float2 h = *reinterpret_cast<float2*>(s->H2 + c * HROW + 2 * p);
      float nx = z.x * h.x + (1.f - z.x) * hx;
      float ny = z.y * h.y + (1.f - z.y) * hy;
      *reinterpret_cast<float2*>(s->H2 + c * HROW + 2 * p) = make_float2(nx, ny);
      osum += nx + ((p == 10) ? 0.f : ny);
    }
  }
  __syncthreads();
  return osum;
}

// ---------------- main kernel: 1 CTA / batch, 256 threads ----------------
__global__ void __launch_bounds__(THREADS, 1)
tgcn_main(const float* __restrict__ x, const float* __restrict__ clsw,
          const float* __restrict__ clsb, float* __restrict__ out) {
  extern __shared__ __align__(16) unsigned char smraw[];
  SM* s = reinterpret_cast<SM*>(smraw);
  const int tid = threadIdx.x;
  const int b = blockIdx.x;
  const int c = tid & 127;
  const int half = tid >> 7;

  for (int i = tid; i < 128; i += THREADS) {
    s->uz[i] = g_c1[i];
    s->ur[i] = g_c1[128 + i];
    s->uh[i] = g_c1[256 + i];
    s->czb[i] = g_c1[384 + i];
    s->crb[i] = g_c1[512 + i];
    s->chb[i] = g_c1[640 + i];
    s->dzb[i] = g_c2[i];
    s->drb[i] = g_c2[128 + i];
    s->dhb[i] = g_c2[256 + i];
    s->clsw[i] = clsw[i];
  }
  for (int i = tid; i < 128 * HROW; i += THREADS) {
    s->H1[i] = 0.f;
    s->H2[i] = 0.f;
    s->XP[i] = 0.f;
    s->XR2[i] = 0.f;
  }
  for (int i = tid; i < 11 * 22; i += THREADS) {
    int p = i / 22, j = i - 22 * p;
    float ax = 0.f, ay = 0.f;
    if (j < NN) {
      ax = g_A[(2 * p) * NN + j];
      if (2 * p + 1 < NN) ay = g_A[(2 * p + 1) * NN + j];
    }
    s->AP[i] = make_float2(ax, ay);
  }
  __syncthreads();

  // precompute YP[t][p] = pair-major (A @ x_t)
  const float* xb = x + (size_t)b * TT * NN;
  for (int i = tid; i < TT * 11; i += THREADS) {
    int t = i / 11, p = i - 11 * t;
    float2 acc = make_float2(0.f, 0.f);
    const float2* ap = s->AP + p * 22;
#pragma unroll
    for (int j = 0; j < NN; j++) {
      float xv = __ldg(xb + t * NN + j);
      acc = ffma2(ap[j], make_float2(xv, xv), acc);
    }
    s->YP[i] = acc;
  }
  __syncthreads();

  float osum_total = 0.f;
  if (half == 0) {
    for (int t = 0; t < TT; t++) osum_total += step_body<0, 6>(s, c, t);
  } else {
    for (int t = 0; t < TT; t++) osum_total += step_body<1, 5>(s, c, t);
  }

  // final reduction
  float v = osum_total * s->clsw[c];
#pragma unroll
  for (int off = 16; off > 0; off >>= 1)
    v += __shfl_down_sync(0xffffffffu, v, off);
  if ((tid & 31) == 0) s->red[tid >> 5] = v;
  __syncthreads();
  if (tid == 0) {
    float tot = 0.f;
#pragma unroll
    for (int w = 0; w < 8; w++) tot += s->red[w];
    out[b] = tot * (1.0f / (TT * NN)) + clsb[0];
  }
}

// ---------------- launch ----------------
extern "C" void kernel_launch(void* const* d_in, const int* in_sizes, int n_in,
                              void* d_out, int out_size) {
  const float* x = (const float*)d_in[0];
  const int* ei = (const int*)d_in[1];
  const float* ew = (const float*)d_in[2];
  const float* Wz1 = (const float*)d_in[3];
  const float* bz1 = (const float*)d_in[4];
  const float* lzw1 = (const float*)d_in[5];
  const float* lzb1 = (const float*)d_in[6];
  const float* Wr1 = (const float*)d_in[7];
  const float* br1 = (const float*)d_in[8];
  const float* lrw1 = (const float*)d_in[9];
  const float* lrb1 = (const float*)d_in[10];
  const float* Wh1 = (const float*)d_in[11];
  const float* bh1 = (const float*)d_in[12];
  const float* lhw1 = (const float*)d_in[13];
  const float* lhb1 = (const float*)d_in[14];
  const float* Wz2 = (const float*)d_in[15];
  const float* bz2 = (const float*)d_in[16];
  const float* lzw2 = (const float*)d_in[17];
  const float* lzb2 = (const float*)d_in[18];
  const float* Wr2 = (const float*)d_in[19];
  const float* br2 = (const float*)d_in[20];
  const float* lrw2 = (const float*)d_in[21];
  const float* lrb2 = (const float*)d_in[22];
  const float* Wh2 = (const float*)d_in[23];
  const float* bh2 = (const float*)d_in[24];
  const float* lhw2 = (const float*)d_in[25];
  const float* lhb2 = (const float*)d_in[26];
  const float* clsw = (const float*)d_in[27];
  const float* clsb = (const float*)d_in[28];
  int E = in_sizes[1] / 2;

  prep_A_kernel<<<1, 32>>>(ei, ew, E);
  prep_W_kernel<<<128, 256>>>(Wz1, bz1, lzw1, lzb1, Wr1, br1, lrw1, lrb1, Wh1,
                              bh1, lhw1, lhb1, Wz2, bz2, lzw2, lzb2, Wr2, br2,
                              lrw2, lrb2, Wh2, bh2, lhw2, lhb2);

  cudaFuncSetAttribute(tgcn_main, cudaFuncAttributeMaxDynamicSharedMemorySize,
                       (int)sizeof(SM));
  tgcn_main<<<BB, THREADS, sizeof(SM)>>>(x, clsw, clsb, (float*)d_out);
}

// round 5
// speedup vs baseline: 3.8802x; 1.2920x over previous
#include <cuda_runtime.h>
#include <math.h>

#define TT 500
#define NN 21
#define BB 64
#define THREADS 384
#define HST 20  // floats per state row (float4-aligned, reduces column bank conflicts)

// ---------------- device scratch ----------------
__device__ __align__(16) float g_A[NN * NN];
__device__ __align__(16) float2 g_P1[128 * 128];  // (lzw1_bot, lrw1_bot)[k][c]
__device__ __align__(16) float g_W1h[128 * 128];  // lhw1_bot[k][c]
__device__ __align__(16) float4 g_P4[128 * 128];  // (Mz, Mr, lzw2_bot, lrw2_bot)[k][c]
__device__ __align__(16) float2 g_P5[128 * 128];  // (Mh, lhw2_bot)[k][c]
__device__ __align__(16) float g_c1[6 * 128];     // uz,ur,uh,czb,crb,chb
__device__ __align__(16) float g_c2[3 * 128];     // dzb,drb,dhb

// ---------------- smem ----------------
struct SM {
  float2 YP[TT * 6];     // local pairs of (A@x_t)
  float2 AP[6 * 22];     // A rows for local pairs (global-j), pad rows/cols zero
  float H1loc[128 * HST];  // own nodes of H1, compact
  float H1rem[128 * HST];  // peer-pushed H1 (peer's compact layout)
  float H2[128 * HST];
  float XR1[128 * HST];
  float XP[128 * HST];
  float XR2[128 * HST];
  float2 ZC[128 * 6];
  float uz[128], ur[128], uh[128], czb[128], crb[128], chb[128];
  float dzb[128], drb[128], dhb[128], clsw[128];
  float peer_sum;
  float red[12];
};

// ---------------- helpers ----------------
__device__ __forceinline__ float2 ffma2(float2 a, float2 b, float2 c) {
  float2 d;
  asm("fma.rn.f32x2 %0, %1, %2, %3;"
      : "=l"(reinterpret_cast<unsigned long long&>(d))
      : "l"(reinterpret_cast<unsigned long long&>(a)),
        "l"(reinterpret_cast<unsigned long long&>(b)),
        "l"(reinterpret_cast<unsigned long long&>(c)));
  return d;
}
__device__ __forceinline__ float tanha(float x) {
  float y;
  asm("tanh.approx.f32 %0, %1;" : "=f"(y) : "f"(x));
  return y;
}
__device__ __forceinline__ float sigma(float x) {
  return fmaf(tanha(0.5f * x), 0.5f, 0.5f);
}
__device__ __forceinline__ unsigned smem_u32(const void* p) {
  unsigned a;
  asm("{ .reg .u64 t; cvta.to.shared.u64 t, %1; cvt.u32.u64 %0, t; }"
      : "=r"(a) : "l"(p));
  return a;
}
__device__ __forceinline__ unsigned mapa_u32(unsigned a, unsigned r) {
  unsigned o;
  asm("mapa.shared::cluster.u32 %0, %1, %2;" : "=r"(o) : "r"(a), "r"(r));
  return o;
}
__device__ __forceinline__ void stc64(unsigned a, float2 v) {
  asm volatile("st.shared::cluster.b64 [%0], %1;"
               :: "r"(a), "l"(reinterpret_cast<const unsigned long long&>(v))
               : "memory");
}
__device__ __forceinline__ void stc32(unsigned a, float v) {
  asm volatile("st.shared::cluster.b32 [%0], %1;" :: "r"(a), "f"(v) : "memory");
}
#define CLUSTER_BAR()                                                     \
  do {                                                                    \
    asm volatile("barrier.cluster.arrive.aligned;" ::: "memory");         \
    asm volatile("barrier.cluster.wait.aligned;" ::: "memory");           \
  } while (0)

template <int NP>
__device__ __forceinline__ void ldp(const float* __restrict__ row, int pl0,
                                    float2* v) {
  if (NP == 2) {
    float4 t = *reinterpret_cast<const float4*>(row + 2 * pl0);
    v[0] = make_float2(t.x, t.y);
    v[1] = make_float2(t.z, t.w);
  } else {
    v[0] = *reinterpret_cast<const float2*>(row + 2 * pl0);
  }
}

// ---------------- prep kernels ----------------
__global__ void prep_A_kernel(const int* __restrict__ ei,
                              const float* __restrict__ ew, int E) {
  if (threadIdx.x != 0 || blockIdx.x != 0) return;
  float deg[NN], dinv[NN];
  for (int n = 0; n < NN; n++) deg[n] = 1.0f;
  for (int e = 0; e < E; e++) deg[ei[E + e]] += ew[e];
  for (int n = 0; n < NN; n++) dinv[n] = (deg[n] > 0.f) ? rsqrtf(deg[n]) : 0.f;
  for (int i = 0; i < NN * NN; i++) g_A[i] = 0.f;
  for (int e = 0; e < E; e++) {
    int s = ei[e], d = ei[E + e];
    g_A[d * NN + s] += dinv[s] * ew[e] * dinv[d];
  }
  for (int n = 0; n < NN; n++) g_A[n * NN + n] += dinv[n] * dinv[n];
}

__global__ void prep_W_kernel(
    const float* Wz1, const float* bz1, const float* lzw1, const float* lzb1,
    const float* Wr1, const float* br1, const float* lrw1, const float* lrb1,
    const float* Wh1, const float* bh1, const float* lhw1, const float* lhb1,
    const float* Wz2, const float* bz2, const float* lzw2, const float* lzb2,
    const float* Wr2, const float* br2, const float* lrw2, const float* lrb2,
    const float* Wh2, const float* bh2, const float* lhw2, const float* lhb2) {
  int t0 = blockIdx.x * blockDim.x + threadIdx.x;
  int nt = gridDim.x * blockDim.x;
  for (int i = t0; i < 128 * 128; i += nt) {
    int k = i >> 7, c = i & 127;
    g_P1[i] = make_float2(lzw1[(128 + k) * 128 + c], lrw1[(128 + k) * 128 + c]);
    g_W1h[i] = lhw1[(128 + k) * 128 + c];
    float mz = 0.f, mr = 0.f, mh = 0.f;
    for (int m = 0; m < 128; m++) {
      mz += Wz2[k * 128 + m] * lzw2[m * 128 + c];
      mr += Wr2[k * 128 + m] * lrw2[m * 128 + c];
      mh += Wh2[k * 128 + m] * lhw2[m * 128 + c];
    }
    g_P4[i] = make_float4(mz, mr, lzw2[(128 + k) * 128 + c],
                          lrw2[(128 + k) * 128 + c]);
    g_P5[i] = make_float2(mh, lhw2[(128 + k) * 128 + c]);
  }
  for (int c = t0; c < 128; c += nt) {
    float uz = 0, ur = 0, uh = 0, cz = 0, cr = 0, ch = 0, dz = 0, dr = 0, dh = 0;
    for (int m = 0; m < 128; m++) {
      uz += Wz1[m] * lzw1[m * 128 + c];
      ur += Wr1[m] * lrw1[m * 128 + c];
      uh += Wh1[m] * lhw1[m * 128 + c];
      cz += bz1[m] * lzw1[m * 128 + c];
      cr += br1[m] * lrw1[m * 128 + c];
      ch += bh1[m] * lhw1[m * 128 + c];
      dz += bz2[m] * lzw2[m * 128 + c];
      dr += br2[m] * lrw2[m * 128 + c];
      dh += bh2[m] * lhw2[m * 128 + c];
    }
    g_c1[0 * 128 + c] = uz;
    g_c1[1 * 128 + c] = ur;
    g_c1[2 * 128 + c] = uh;
    g_c1[3 * 128 + c] = cz + lzb1[c];
    g_c1[4 * 128 + c] = cr + lrb1[c];
    g_c1[5 * 128 + c] = ch + lhb1[c];
    g_c2[0 * 128 + c] = dz + lzb2[c];
    g_c2[1 * 128 + c] = dr + lrb2[c];
    g_c2[2 * 128 + c] = dh + lhb2[c];
  }
}

// ---------------- per-thread recurrence ----------------
template <int NP, bool MASK>
__device__ float run_steps(SM* __restrict__ s, const int c, const int pl0,
                           const unsigned peer_h1,
                           const float* __restrict__ bufA,
                           const float* __restrict__ bufB) {
  float osum_total = 0.f;
  const float uzv = s->uz[c], urv = s->ur[c], uhv = s->uh[c];
  const float czv = s->czb[c], crv = s->crb[c], chv = s->chb[c];
  const float dzv = s->dzb[c], drv = s->drb[c], dhv = s->dhb[c];

  for (int t = 0; t < TT; t++) {
    // ---- pass 1: layer1 z & r gates (dot over H1loc) ----
    {
      float2 az[NP], ar[NP];
#pragma unroll
      for (int i = 0; i < NP; i++) az[i] = ar[i] = make_float2(0.f, 0.f);
      const float2* w = g_P1 + c;
#pragma unroll 8
      for (int k = 0; k < 128; k++) {
        float2 wv = __ldg(reinterpret_cast<const float2*>(w + k * 128));
        float2 h[NP];
        ldp<NP>(s->H1loc + k * HST, pl0, h);
        float2 wz2 = make_float2(wv.x, wv.x), wr2 = make_float2(wv.y, wv.y);
#pragma unroll
        for (int i = 0; i < NP; i++) {
          az[i] = ffma2(h[i], wz2, az[i]);
          ar[i] = ffma2(h[i], wr2, ar[i]);
        }
      }
#pragma unroll
      for (int i = 0; i < NP; i++) {
        int pl = pl0 + i;
        float2 y = s->YP[t * 6 + pl];
        float zx = sigma(az[i].x + y.x * uzv + czv);
        float zy = sigma(az[i].y + y.y * uzv + czv);
        float rx = sigma(ar[i].x + y.x * urv + crv);
        float ry = sigma(ar[i].y + y.y * urv + crv);
        s->ZC[c * 6 + pl] = make_float2(zx, zy);
        float2 h = *reinterpret_cast<float2*>(s->H1loc + c * HST + 2 * pl);
        *reinterpret_cast<float2*>(s->XR1 + c * HST + 2 * pl) =
            make_float2(h.x * rx, h.y * ry);
      }
    }
    __syncthreads();

    // ---- pass 2: layer1 h-gate + H1 update + push to peer ----
    {
      float2 ah[NP];
#pragma unroll
      for (int i = 0; i < NP; i++) ah[i] = make_float2(0.f, 0.f);
      const float* w = g_W1h + c;
#pragma unroll 8
      for (int k = 0; k < 128; k++) {
        float wv = __ldg(w + k * 128);
        float2 h[NP];
        ldp<NP>(s->XR1 + k * HST, pl0, h);
        float2 w2 = make_float2(wv, wv);
#pragma unroll
        for (int i = 0; i < NP; i++) ah[i] = ffma2(h[i], w2, ah[i]);
      }
#pragma unroll
      for (int i = 0; i < NP; i++) {
        int pl = pl0 + i;
        float2 y = s->YP[t * 6 + pl];
        float hx = tanha(ah[i].x + y.x * uhv + chv);
        float hy = tanha(ah[i].y + y.y * uhv + chv);
        float2 z = s->ZC[c * 6 + pl];
        float2 h = *reinterpret_cast<float2*>(s->H1loc + c * HST + 2 * pl);
        float2 hn = make_float2(z.x * h.x + (1.f - z.x) * hx,
                                z.y * h.y + (1.f - z.y) * hy);
        *reinterpret_cast<float2*>(s->H1loc + c * HST + 2 * pl) = hn;
        stc64(peer_h1 + (unsigned)(c * HST + 2 * pl) * 4u, hn);
      }
    }
    CLUSTER_BAR();

    // ---- pass 3: node mix  XP[k][local pairs] = A-rows · full H1 row k ----
    {
      const int k = c;
      float hj[22];
      {
        const float* rA = bufA + k * HST;  // nodes 0-9
        float4 a0 = *reinterpret_cast<const float4*>(rA);
        float4 a1 = *reinterpret_cast<const float4*>(rA + 4);
        float2 a2 = *reinterpret_cast<const float2*>(rA + 8);
        hj[0] = a0.x; hj[1] = a0.y; hj[2] = a0.z; hj[3] = a0.w;
        hj[4] = a1.x; hj[5] = a1.y; hj[6] = a1.z; hj[7] = a1.w;
        hj[8] = a2.x; hj[9] = a2.y;
        const float* rB = bufB + k * HST;  // nodes 10-21 (21 = pad)
        float4 b0 = *reinterpret_cast<const float4*>(rB);
        float4 b1 = *reinterpret_cast<const float4*>(rB + 4);
        float4 b2 = *reinterpret_cast<const float4*>(rB + 8);
        hj[10] = b0.x; hj[11] = b0.y; hj[12] = b0.z; hj[13] = b0.w;
        hj[14] = b1.x; hj[15] = b1.y; hj[16] = b1.z; hj[17] = b1.w;
        hj[18] = b2.x; hj[19] = b2.y; hj[20] = b2.z; hj[21] = b2.w;
      }
#pragma unroll
      for (int i = 0; i < NP; i++) {
        int pl = pl0 + i;
        const float2* ap = s->AP + pl * 22;
        float2 a = make_float2(0.f, 0.f);
#pragma unroll
        for (int j = 0; j < NN; j++)
          a = ffma2(ap[j], make_float2(hj[j], hj[j]), a);
        *reinterpret_cast<float2*>(s->XP + k * HST + 2 * pl) = a;
      }
    }
    __syncthreads();

    // ---- pass 4: layer2 z & r (fused XP·M + H2·W) ----
    {
      float2 az[NP], ar[NP];
#pragma unroll
      for (int i = 0; i < NP; i++) az[i] = ar[i] = make_float2(0.f, 0.f);
      const float4* w = g_P4 + c;
#pragma unroll 4
      for (int k = 0; k < 128; k++) {
        float4 wv = __ldg(w + k * 128);
        float2 xv[NP], hv[NP];
        ldp<NP>(s->XP + k * HST, pl0, xv);
        ldp<NP>(s->H2 + k * HST, pl0, hv);
        float2 mz2 = make_float2(wv.x, wv.x), mr2 = make_float2(wv.y, wv.y);
        float2 vz2 = make_float2(wv.z, wv.z), vr2 = make_float2(wv.w, wv.w);
#pragma unroll
        for (int i = 0; i < NP; i++) {
          az[i] = ffma2(xv[i], mz2, az[i]);
          az[i] = ffma2(hv[i], vz2, az[i]);
          ar[i] = ffma2(xv[i], mr2, ar[i]);
          ar[i] = ffma2(hv[i], vr2, ar[i]);
        }
      }
#pragma unroll
      for (int i = 0; i < NP; i++) {
        int pl = pl0 + i;
        float zx = sigma(az[i].x + dzv);
        float zy = sigma(az[i].y + dzv);
        float rx = sigma(ar[i].x + drv);
        float ry = sigma(ar[i].y + drv);
        s->ZC[c * 6 + pl] = make_float2(zx, zy);
        float2 h = *reinterpret_cast<float2*>(s->H2 + c * HST + 2 * pl);
        *reinterpret_cast<float2*>(s->XR2 + c * HST + 2 * pl) =
            make_float2(h.x * rx, h.y * ry);
      }
    }
    __syncthreads();

    // ---- pass 5: layer2 h-gate + H2 update + output accum ----
    {
      float2 ah[NP];
#pragma unroll
      for (int i = 0; i < NP; i++) ah[i] = make_float2(0.f, 0.f);
      const float2* w = g_P5 + c;
#pragma unroll 4
      for (int k = 0; k < 128; k++) {
        float2 wv = __ldg(reinterpret_cast<const float2*>(w + k * 128));
        float2 xv[NP], rv[NP];
        ldp<NP>(s->XP + k * HST, pl0, xv);
        ldp<NP>(s->XR2 + k * HST, pl0, rv);
        float2 m2 = make_float2(wv.x, wv.x), w2 = make_float2(wv.y, wv.y);
#pragma unroll
        for (int i = 0; i < NP; i++) {
          ah[i] = ffma2(xv[i], m2, ah[i]);
          ah[i] = ffma2(rv[i], w2, ah[i]);
        }
      }
      float os = 0.f;
#pragma unroll
      for (int i = 0; i < NP; i++) {
        int pl = pl0 + i;
        float hx = tanha(ah[i].x + dhv);
        float hy = tanha(ah[i].y + dhv);
        float2 z = s->ZC[c * 6 + pl];
        float2 h = *reinterpret_cast<float2*>(s->H2 + c * HST + 2 * pl);
        float nx = z.x * h.x + (1.f - z.x) * hx;
        float ny = z.y * h.y + (1.f - z.y) * hy;
        *reinterpret_cast<float2*>(s->H2 + c * HST + 2 * pl) =
            make_float2(nx, ny);
        if (MASK && i == NP - 1) os += nx;   // node 21 is padding
        else os += nx + ny;
      }
      osum_total += os;
    }
    __syncthreads();
  }
  return osum_total;
}

// ---------------- main kernel: 2-CTA cluster per batch ----------------
__global__ void __launch_bounds__(THREADS, 1) __cluster_dims__(2, 1, 1)
tgcn_main(const float* __restrict__ x, const float* __restrict__ clsw,
          const float* __restrict__ clsb, float* __restrict__ out) {
  extern __shared__ __align__(16) unsigned char smraw[];
  SM* s = reinterpret_cast<SM*>(smraw);
  const int tid = threadIdx.x;
  const int rank = blockIdx.x & 1;
  const int b = blockIdx.x >> 1;
  const int c = tid & 127;
  const int sub = tid >> 7;  // 0..2
  const int nploc = rank ? 6 : 5;
  const int gbase = rank ? 5 : 0;
  const int pl0 = 2 * sub;

  for (int i = tid; i < 128; i += THREADS) {
    s->uz[i] = g_c1[i];
    s->ur[i] = g_c1[128 + i];
    s->uh[i] = g_c1[256 + i];
    s->czb[i] = g_c1[384 + i];
    s->crb[i] = g_c1[512 + i];
    s->chb[i] = g_c1[640 + i];
    s->dzb[i] = g_c2[i];
    s->drb[i] = g_c2[128 + i];
    s->dhb[i] = g_c2[256 + i];
    s->clsw[i] = clsw[i];
  }
  for (int i = tid; i < 128 * HST; i += THREADS) {
    s->H1loc[i] = 0.f;
    s->H1rem[i] = 0.f;
    s->H2[i] = 0.f;
    s->XR1[i] = 0.f;
    s->XP[i] = 0.f;
    s->XR2[i] = 0.f;
  }
  for (int i = tid; i < 6 * 22; i += THREADS) {
    int pl = i / 22, j = i - 22 * pl;
    float ax = 0.f, ay = 0.f;
    if (pl < nploc && j < NN) {
      int gp = gbase + pl;
      ax = g_A[(2 * gp) * NN + j];
      if (2 * gp + 1 < NN) ay = g_A[(2 * gp + 1) * NN + j];
    }
    s->AP[i] = make_float2(ax, ay);
  }
  __syncthreads();

  // precompute local-pair Y for all steps
  const float* xb = x + (size_t)b * TT * NN;
  for (int i = tid; i < TT * nploc; i += THREADS) {
    int t = i / nploc, pl = i - t * nploc;
    const float2* ap = s->AP + pl * 22;
    float2 acc = make_float2(0.f, 0.f);
#pragma unroll
    for (int j = 0; j < NN; j++) {
      float xv = __ldg(xb + t * NN + j);
      acc = ffma2(ap[j], make_float2(xv, xv), acc);
    }
    s->YP[t * 6 + pl] = acc;
  }
  CLUSTER_BAR();  // peer smem initialized before any DSMEM push

  const unsigned peer_h1 = mapa_u32(smem_u32(s->H1rem), (unsigned)(rank ^ 1));
  const float* bufA = rank ? s->H1rem : s->H1loc;  // nodes 0-9
  const float* bufB = rank ? s->H1loc : s->H1rem;  // nodes 10-21

  float osum;
  const int np = (rank == 0 && sub == 2) ? 1 : 2;
  const bool mask = (rank == 1 && sub == 2);
  if (np == 1)
    osum = run_steps<1, false>(s, c, pl0, peer_h1, bufA, bufB);
  else if (mask)
    osum = run_steps<2, true>(s, c, pl0, peer_h1, bufA, bufB);
  else
    osum = run_steps<2, false>(s, c, pl0, peer_h1, bufA, bufB);

  // CTA reduction of clsw-weighted sums
  float v = osum * s->clsw[c];
#pragma unroll
  for (int off = 16; off > 0; off >>= 1)
    v += __shfl_down_sync(0xffffffffu, v, off);
  if ((tid & 31) == 0) s->red[tid >> 5] = v;
  if (tid == 0) s->peer_sum = 0.f;
  __syncthreads();
  float S = 0.f;
  if (tid == 0) {
#pragma unroll
    for (int w = 0; w < 12; w++) S += s->red[w];
    if (rank == 1) stc32(mapa_u32(smem_u32(&s->peer_sum), 0u), S);
  }
  CLUSTER_BAR();
  if (rank == 0 && tid == 0)
    out[b] = (S + s->peer_sum) * (1.0f / (TT * NN)) + clsb[0];
}

// ---------------- launch ----------------
extern "C" void kernel_launch(void* const* d_in, const int* in_sizes, int n_in,
                              void* d_out, int out_size) {
  const float* x = (const float*)d_in[0];
  const int* ei = (const int*)d_in[1];
  const float* ew = (const float*)d_in[2];
  const float* Wz1 = (const float*)d_in[3];
  const float* bz1 = (const float*)d_in[4];
  const float* lzw1 = (const float*)d_in[5];
  const float* lzb1 = (const float*)d_in[6];
  const float* Wr1 = (const float*)d_in[7];
  const float* br1 = (const float*)d_in[8];
  const float* lrw1 = (const float*)d_in[9];
  const float* lrb1 = (const float*)d_in[10];
  const float* Wh1 = (const float*)d_in[11];
  const float* bh1 = (const float*)d_in[12];
  const float* lhw1 = (const float*)d_in[13];
  const float* lhb1 = (const float*)d_in[14];
  const float* Wz2 = (const float*)d_in[15];
  const float* bz2 = (const float*)d_in[16];
  const float* lzw2 = (const float*)d_in[17];
  const float* lzb2 = (const float*)d_in[18];
  const float* Wr2 = (const float*)d_in[19];
  const float* br2 = (const float*)d_in[20];
  const float* lrw2 = (const float*)d_in[21];
  const float* lrb2 = (const float*)d_in[22];
  const float* Wh2 = (const float*)d_in[23];
  const float* bh2 = (const float*)d_in[24];
  const float* lhw2 = (const float*)d_in[25];
  const float* lhb2 = (const float*)d_in[26];
  const float* clsw = (const float*)d_in[27];
  const float* clsb = (const float*)d_in[28];
  int E = in_sizes[1] / 2;

  prep_A_kernel<<<1, 32>>>(ei, ew, E);
  prep_W_kernel<<<128, 256>>>(Wz1, bz1, lzw1, lzb1, Wr1, br1, lrw1, lrb1, Wh1,
                              bh1, lhw1, lhb1, Wz2, bz2, lzw2, lzb2, Wr2, br2,
                              lrw2, lrb2, Wh2, bh2, lhw2, lhb2);

  cudaFuncSetAttribute(tgcn_main, cudaFuncAttributeMaxDynamicSharedMemorySize,
                       (int)sizeof(SM));
  tgcn_main<<<2 * BB, THREADS, sizeof(SM)>>>(x, clsw, clsb, (float*)d_out);
}

// round 6
// speedup vs baseline: 4.5042x; 1.1608x over previous
#include <cuda_runtime.h>
#include <math.h>

#define TT 500
#define NN 21
#define BB 64
#define THREADS 384
#define HST 20  // floats per state row

// ---------------- device scratch ----------------
__device__ __align__(16) float g_A[NN * NN];
__device__ __align__(16) float2 g_P1[128 * 128];  // (lzw1_bot, lrw1_bot)[k][c]  128KB -> chunks 0-3
__device__ __align__(16) float g_W1h[128 * 128];  // lhw1_bot[k][c]              64KB -> chunks 4-5
__device__ __align__(16) float4 g_P4[128 * 128];  // (Mz,Mr,lzw2_bot,lrw2_bot)  256KB -> chunks 6-13
__device__ __align__(16) float2 g_P5[128 * 128];  // (Mh, lhw2_bot)             128KB -> chunks 14-17
__device__ __align__(16) float g_c1[6 * 128];
__device__ __align__(16) float g_c2[3 * 128];

// ---------------- smem ----------------
struct SM {
  float4 WBUF[2][2048];  // double-buffered 32KB weight chunks
  float2 YP[TT * 6];
  float2 AP[6 * 22];
  float H1loc[128 * HST];
  float H1rem[128 * HST];
  float H2[128 * HST];
  float XR1[128 * HST];
  float XP[128 * HST];
  float XR2[128 * HST];
  float2 ZC[128 * 6];
  float uz[128], ur[128], uh[128], czb[128], crb[128], chb[128];
  float dzb[128], drb[128], dhb[128], clsw[128];
  float peer_sum;
  float red[12];
};

// ---------------- helpers ----------------
__device__ __forceinline__ float2 ffma2(float2 a, float2 b, float2 c) {
  float2 d;
  asm("fma.rn.f32x2 %0, %1, %2, %3;"
      : "=l"(reinterpret_cast<unsigned long long&>(d))
      : "l"(reinterpret_cast<unsigned long long&>(a)),
        "l"(reinterpret_cast<unsigned long long&>(b)),
        "l"(reinterpret_cast<unsigned long long&>(c)));
  return d;
}
__device__ __forceinline__ float tanha(float x) {
  float y;
  asm("tanh.approx.f32 %0, %1;" : "=f"(y) : "f"(x));
  return y;
}
__device__ __forceinline__ float sigma(float x) {
  return fmaf(tanha(0.5f * x), 0.5f, 0.5f);
}
__device__ __forceinline__ unsigned smem_u32(const void* p) {
  unsigned a;
  asm("{ .reg .u64 t; cvta.to.shared.u64 t, %1; cvt.u32.u64 %0, t; }"
      : "=r"(a) : "l"(p));
  return a;
}
__device__ __forceinline__ unsigned mapa_u32(unsigned a, unsigned r) {
  unsigned o;
  asm("mapa.shared::cluster.u32 %0, %1, %2;" : "=r"(o) : "r"(a), "r"(r));
  return o;
}
__device__ __forceinline__ void stc64(unsigned a, float2 v) {
  asm volatile("st.shared::cluster.b64 [%0], %1;"
               :: "r"(a), "l"(reinterpret_cast<const unsigned long long&>(v))
               : "memory");
}
__device__ __forceinline__ void stc32(unsigned a, float v) {
  asm volatile("st.shared::cluster.b32 [%0], %1;" :: "r"(a), "f"(v) : "memory");
}
#define CLUSTER_BAR()                                             \
  do {                                                            \
    asm volatile("barrier.cluster.arrive.aligned;" ::: "memory"); \
    asm volatile("barrier.cluster.wait.aligned;" ::: "memory");   \
  } while (0)

template <int NP>
__device__ __forceinline__ void ldp(const float* __restrict__ row, int pl0,
                                    float2* v) {
  if (NP == 2) {
    float4 t = *reinterpret_cast<const float4*>(row + 2 * pl0);
    v[0] = make_float2(t.x, t.y);
    v[1] = make_float2(t.z, t.w);
  } else {
    v[0] = *reinterpret_cast<const float2*>(row + 2 * pl0);
  }
}

// issue cp.async for one 32KB chunk (2048 float4) + commit
__device__ __forceinline__ void issue_chunk(SM* s, int nx, int tid) {
  const float4* src;
  if (nx < 4) src = reinterpret_cast<const float4*>(g_P1) + nx * 2048;
  else if (nx < 6) src = reinterpret_cast<const float4*>(g_W1h) + (nx - 4) * 2048;
  else if (nx < 14) src = reinterpret_cast<const float4*>(g_P4) + (nx - 6) * 2048;
  else src = reinterpret_cast<const float4*>(g_P5) + (nx - 14) * 2048;
  float4* dst = s->WBUF[nx & 1];
  for (int j = tid; j < 2048; j += THREADS) {
    unsigned a = smem_u32(dst + j);
    asm volatile("cp.async.cg.shared.global [%0], [%1], 16;"
                 :: "r"(a), "l"(src + j) : "memory");
  }
  asm volatile("cp.async.commit_group;" ::: "memory");
}

// segment boundary: wait current chunk, sync, prefetch next
__device__ __forceinline__ void seg_begin(SM* s, int g, int tid, bool pref) {
  asm volatile("cp.async.wait_group 0;" ::: "memory");
  __syncthreads();
  if (pref) {
    int nx = g + 1;
    if (nx == 18) nx = 0;
    issue_chunk(s, nx, tid);
  }
}

// ---------------- prep kernels ----------------
__global__ void prep_A_kernel(const int* __restrict__ ei,
                              const float* __restrict__ ew, int E) {
  if (threadIdx.x != 0 || blockIdx.x != 0) return;
  float deg[NN], dinv[NN];
  for (int n = 0; n < NN; n++) deg[n] = 1.0f;
  for (int e = 0; e < E; e++) deg[ei[E + e]] += ew[e];
  for (int n = 0; n < NN; n++) dinv[n] = (deg[n] > 0.f) ? rsqrtf(deg[n]) : 0.f;
  for (int i = 0; i < NN * NN; i++) g_A[i] = 0.f;
  for (int e = 0; e < E; e++) {
    int s = ei[e], d = ei[E + e];
    g_A[d * NN + s] += dinv[s] * ew[e] * dinv[d];
  }
  for (int n = 0; n < NN; n++) g_A[n * NN + n] += dinv[n] * dinv[n];
}

__global__ void prep_W_kernel(
    const float* Wz1, const float* bz1, const float* lzw1, const float* lzb1,
    const float* Wr1, const float* br1, const float* lrw1, const float* lrb1,
    const float* Wh1, const float* bh1, const float* lhw1, const float* lhb1,
    const float* Wz2, const float* bz2, const float* lzw2, const float* lzb2,
    const float* Wr2, const float* br2, const float* lrw2, const float* lrb2,
    const float* Wh2, const float* bh2, const float* lhw2, const float* lhb2) {
  int t0 = blockIdx.x * blockDim.x + threadIdx.x;
  int nt = gridDim.x * blockDim.x;
  for (int i = t0; i < 128 * 128; i += nt) {
    int k = i >> 7, c = i & 127;
    g_P1[i] = make_float2(lzw1[(128 + k) * 128 + c], lrw1[(128 + k) * 128 + c]);
    g_W1h[i] = lhw1[(128 + k) * 128 + c];
    float mz = 0.f, mr = 0.f, mh = 0.f;
    for (int m = 0; m < 128; m++) {
      mz += Wz2[k * 128 + m] * lzw2[m * 128 + c];
      mr += Wr2[k * 128 + m] * lrw2[m * 128 + c];
      mh += Wh2[k * 128 + m] * lhw2[m * 128 + c];
    }
    g_P4[i] = make_float4(mz, mr, lzw2[(128 + k) * 128 + c],
                          lrw2[(128 + k) * 128 + c]);
    g_P5[i] = make_float2(mh, lhw2[(128 + k) * 128 + c]);
  }
  for (int c = t0; c < 128; c += nt) {
    float uz = 0, ur = 0, uh = 0, cz = 0, cr = 0, ch = 0, dz = 0, dr = 0, dh = 0;
    for (int m = 0; m < 128; m++) {
      uz += Wz1[m] * lzw1[m * 128 + c];
      ur += Wr1[m] * lrw1[m * 128 + c];
      uh += Wh1[m] * lhw1[m * 128 + c];
      cz += bz1[m] * lzw1[m * 128 + c];
      cr += br1[m] * lrw1[m * 128 + c];
      ch += bh1[m] * lhw1[m * 128 + c];
      dz += bz2[m] * lzw2[m * 128 + c];
      dr += br2[m] * lrw2[m * 128 + c];
      dh += bh2[m] * lhw2[m * 128 + c];
    }
    g_c1[0 * 128 + c] = uz;
    g_c1[1 * 128 + c] = ur;
    g_c1[2 * 128 + c] = uh;
    g_c1[3 * 128 + c] = cz + lzb1[c];
    g_c1[4 * 128 + c] = cr + lrb1[c];
    g_c1[5 * 128 + c] = ch + lhb1[c];
    g_c2[0 * 128 + c] = dz + lzb2[c];
    g_c2[1 * 128 + c] = dr + lrb2[c];
    g_c2[2 * 128 + c] = dh + lhb2[c];
  }
}

// ---------------- per-thread recurrence ----------------
template <int NP, bool MASK>
__device__ float run_steps(SM* __restrict__ s, const int c, const int pl0,
                           const unsigned peer_h1,
                           const float* __restrict__ bufA,
                           const float* __restrict__ bufB, const int tid) {
  float osum_total = 0.f;
  const float uzv = s->uz[c], urv = s->ur[c], uhv = s->uh[c];
  const float czv = s->czb[c], crv = s->crb[c], chv = s->chb[c];
  const float dzv = s->dzb[c], drv = s->drb[c], dhv = s->dhb[c];

  for (int t = 0; t < TT; t++) {
    const bool nlast = (t != TT - 1);
    int g = 0;

    // ---- pass 1: layer1 z & r gates (chunks 0-3, KC=32) ----
    {
      float2 az[NP], ar[NP];
#pragma unroll
      for (int i = 0; i < NP; i++) az[i] = ar[i] = make_float2(0.f, 0.f);
      for (int ch = 0; ch < 4; ch++) {
        seg_begin(s, g, tid, true);
        const float2* W = reinterpret_cast<const float2*>(s->WBUF[g & 1]);
        const float* Hb = s->H1loc + ch * 32 * HST;
#pragma unroll 8
        for (int k = 0; k < 32; k++) {
          float2 wv = W[k * 128 + c];
          float2 h[NP];
          ldp<NP>(Hb + k * HST, pl0, h);
          float2 wz2 = make_float2(wv.x, wv.x), wr2 = make_float2(wv.y, wv.y);
#pragma unroll
          for (int i = 0; i < NP; i++) {
            az[i] = ffma2(h[i], wz2, az[i]);
            ar[i] = ffma2(h[i], wr2, ar[i]);
          }
        }
        g++;
      }
#pragma unroll
      for (int i = 0; i < NP; i++) {
        int pl = pl0 + i;
        float2 y = s->YP[t * 6 + pl];
        float zx = sigma(az[i].x + y.x * uzv + czv);
        float zy = sigma(az[i].y + y.y * uzv + czv);
        float rx = sigma(ar[i].x + y.x * urv + crv);
        float ry = sigma(ar[i].y + y.y * urv + crv);
        s->ZC[c * 6 + pl] = make_float2(zx, zy);
        float2 h = *reinterpret_cast<float2*>(s->H1loc + c * HST + 2 * pl);
        *reinterpret_cast<float2*>(s->XR1 + c * HST + 2 * pl) =
            make_float2(h.x * rx, h.y * ry);
      }
    }

    // ---- pass 2: layer1 h-gate (chunks 4-5, KC=64) ----
    {
      float2 ah[NP];
#pragma unroll
      for (int i = 0; i < NP; i++) ah[i] = make_float2(0.f, 0.f);
      for (int ch = 0; ch < 2; ch++) {
        seg_begin(s, g, tid, true);
        const float* Wf = reinterpret_cast<const float*>(s->WBUF[g & 1]);
        const float* Hb = s->XR1 + ch * 64 * HST;
#pragma unroll 8
        for (int k = 0; k < 64; k++) {
          float wv = Wf[k * 128 + c];
          float2 h[NP];
          ldp<NP>(Hb + k * HST, pl0, h);
          float2 w2 = make_float2(wv, wv);
#pragma unroll
          for (int i = 0; i < NP; i++) ah[i] = ffma2(h[i], w2, ah[i]);
        }
        g++;
      }
#pragma unroll
      for (int i = 0; i < NP; i++) {
        int pl = pl0 + i;
        float2 y = s->YP[t * 6 + pl];
        float hx = tanha(ah[i].x + y.x * uhv + chv);
        float hy = tanha(ah[i].y + y.y * uhv + chv);
        float2 z = s->ZC[c * 6 + pl];
        float2 h = *reinterpret_cast<float2*>(s->H1loc + c * HST + 2 * pl);
        float2 hn = make_float2(z.x * h.x + (1.f - z.x) * hx,
                                z.y * h.y + (1.f - z.y) * hy);
        *reinterpret_cast<float2*>(s->H1loc + c * HST + 2 * pl) = hn;
        stc64(peer_h1 + (unsigned)(c * HST + 2 * pl) * 4u, hn);
      }
    }
    CLUSTER_BAR();

    // ---- pass 3: node mix (no weights; pass4 chunk0 copy in flight) ----
    {
      const int k = c;
      float hj[22];
      {
        const float* rA = bufA + k * HST;
        float4 a0 = *reinterpret_cast<const float4*>(rA);
        float4 a1 = *reinterpret_cast<const float4*>(rA + 4);
        float2 a2 = *reinterpret_cast<const float2*>(rA + 8);
        hj[0] = a0.x; hj[1] = a0.y; hj[2] = a0.z; hj[3] = a0.w;
        hj[4] = a1.x; hj[5] = a1.y; hj[6] = a1.z; hj[7] = a1.w;
        hj[8] = a2.x; hj[9] = a2.y;
        const float* rB = bufB + k * HST;
        float4 b0 = *reinterpret_cast<const float4*>(rB);
        float4 b1 = *reinterpret_cast<const float4*>(rB + 4);
        float4 b2 = *reinterpret_cast<const float4*>(rB + 8);
        hj[10] = b0.x; hj[11] = b0.y; hj[12] = b0.z; hj[13] = b0.w;
        hj[14] = b1.x; hj[15] = b1.y; hj[16] = b1.z; hj[17] = b1.w;
        hj[18] = b2.x; hj[19] = b2.y; hj[20] = b2.z; hj[21] = b2.w;
      }
#pragma unroll
      for (int i = 0; i < NP; i++) {
        int pl = pl0 + i;
        const float2* ap = s->AP + pl * 22;
        float2 a = make_float2(0.f, 0.f);
#pragma unroll
        for (int j = 0; j < NN; j++)
          a = ffma2(ap[j], make_float2(hj[j], hj[j]), a);
        *reinterpret_cast<float2*>(s->XP + k * HST + 2 * pl) = a;
      }
    }

    // ---- pass 4: layer2 z & r fused (chunks 6-13, KC=16) ----
    {
      float2 az[NP], ar[NP];
#pragma unroll
      for (int i = 0; i < NP; i++) az[i] = ar[i] = make_float2(0.f, 0.f);
      for (int ch = 0; ch < 8; ch++) {
        seg_begin(s, g, tid, true);
        const float4* W4 = s->WBUF[g & 1];
        const float* Xb = s->XP + ch * 16 * HST;
        const float* Hb = s->H2 + ch * 16 * HST;
#pragma unroll 8
        for (int k = 0; k < 16; k++) {
          float4 wv = W4[k * 128 + c];
          float2 xv[NP], hv[NP];
          ldp<NP>(Xb + k * HST, pl0, xv);
          ldp<NP>(Hb + k * HST, pl0, hv);
          float2 mz2 = make_float2(wv.x, wv.x), mr2 = make_float2(wv.y, wv.y);
          float2 vz2 = make_float2(wv.z, wv.z), vr2 = make_float2(wv.w, wv.w);
#pragma unroll
          for (int i = 0; i < NP; i++) {
            az[i] = ffma2(xv[i], mz2, az[i]);
            az[i] = ffma2(hv[i], vz2, az[i]);
            ar[i] = ffma2(xv[i], mr2, ar[i]);
            ar[i] = ffma2(hv[i], vr2, ar[i]);
          }
        }
        g++;
      }
#pragma unroll
      for (int i = 0; i < NP; i++) {
        int pl = pl0 + i;
        float zx = sigma(az[i].x + dzv);
        float zy = sigma(az[i].y + dzv);
        float rx = sigma(ar[i].x + drv);
        float ry = sigma(ar[i].y + drv);
        s->ZC[c * 6 + pl] = make_float2(zx, zy);
        float2 h = *reinterpret_cast<float2*>(s->H2 + c * HST + 2 * pl);
        *reinterpret_cast<float2*>(s->XR2 + c * HST + 2 * pl) =
            make_float2(h.x * rx, h.y * ry);
      }
    }

    // ---- pass 5: layer2 h-gate + H2 update (chunks 14-17, KC=32) ----
    {
      float2 ah[NP];
#pragma unroll
      for (int i = 0; i < NP; i++) ah[i] = make_float2(0.f, 0.f);
      for (int ch = 0; ch < 4; ch++) {
        seg_begin(s, g, tid, nlast || ch != 3);
        const float2* W2 = reinterpret_cast<const float2*>(s->WBUF[g & 1]);
        const float* Xb = s->XP + ch * 32 * HST;
        const float* Rb = s->XR2 + ch * 32 * HST;
#pragma unroll 8
        for (int k = 0; k < 32; k++) {
          float2 wv = W2[k * 128 + c];
          float2 xv[NP], rv[NP];
          ldp<NP>(Xb + k * HST, pl0, xv);
          ldp<NP>(Rb + k * HST, pl0, rv);
          float2 m2 = make_float2(wv.x, wv.x), w2 = make_float2(wv.y, wv.y);
#pragma unroll
          for (int i = 0; i < NP; i++) {
            ah[i] = ffma2(xv[i], m2, ah[i]);
            ah[i] = ffma2(rv[i], w2, ah[i]);
          }
        }
        g++;
      }
      float os = 0.f;
#pragma unroll
      for (int i = 0; i < NP; i++) {
        int pl = pl0 + i;
        float hx = tanha(ah[i].x + dhv);
        float hy = tanha(ah[i].y + dhv);
        float2 z = s->ZC[c * 6 + pl];
        float2 h = *reinterpret_cast<float2*>(s->H2 + c * HST + 2 * pl);
        float nx = z.x * h.x + (1.f - z.x) * hx;
        float ny = z.y * h.y + (1.f - z.y) * hy;
        *reinterpret_cast<float2*>(s->H2 + c * HST + 2 * pl) =
            make_float2(nx, ny);
        if (MASK && i == NP - 1) os += nx;
        else os += nx + ny;
      }
      osum_total += os;
    }
  }
  return osum_total;
}

// ---------------- main kernel: 2-CTA cluster per batch ----------------
__global__ void __launch_bounds__(THREADS, 1) __cluster_dims__(2, 1, 1)
tgcn_main(const float* __restrict__ x, const float* __restrict__ clsw,
          const float* __restrict__ clsb, float* __restrict__ out) {
  extern __shared__ __align__(16) unsigned char smraw[];
  SM* s = reinterpret_cast<SM*>(smraw);
  const int tid = threadIdx.x;
  const int rank = blockIdx.x & 1;
  const int b = blockIdx.x >> 1;
  const int c = tid & 127;
  const int sub = tid >> 7;
  const int nploc = rank ? 6 : 5;
  const int gbase = rank ? 5 : 0;
  const int pl0 = 2 * sub;

  for (int i = tid; i < 128; i += THREADS) {
    s->uz[i] = g_c1[i];
    s->ur[i] = g_c1[128 + i];
    s->uh[i] = g_c1[256 + i];
    s->czb[i] = g_c1[384 + i];
    s->crb[i] = g_c1[512 + i];
    s->chb[i] = g_c1[640 + i];
    s->dzb[i] = g_c2[i];
    s->drb[i] = g_c2[128 + i];
    s->dhb[i] = g_c2[256 + i];
    s->clsw[i] = clsw[i];
  }
  for (int i = tid; i < 128 * HST; i += THREADS) {
    s->H1loc[i] = 0.f;
    s->H1rem[i] = 0.f;
    s->H2[i] = 0.f;
    s->XR1[i] = 0.f;
    s->XP[i] = 0.f;
    s->XR2[i] = 0.f;
  }
  for (int i = tid; i < 6 * 22; i += THREADS) {
    int pl = i / 22, j = i - 22 * pl;
    float ax = 0.f, ay = 0.f;
    if (pl < nploc && j < NN) {
      int gp = gbase + pl;
      ax = g_A[(2 * gp) * NN + j];
      if (2 * gp + 1 < NN) ay = g_A[(2 * gp + 1) * NN + j];
    }
    s->AP[i] = make_float2(ax, ay);
  }
  __syncthreads();

  // precompute local-pair Y for all steps
  const float* xb = x + (size_t)b * TT * NN;
  for (int i = tid; i < TT * nploc; i += THREADS) {
    int t = i / nploc, pl = i - t * nploc;
    const float2* ap = s->AP + pl * 22;
    float2 acc = make_float2(0.f, 0.f);
#pragma unroll
    for (int j = 0; j < NN; j++) {
      float xv = __ldg(xb + t * NN + j);
      acc = ffma2(ap[j], make_float2(xv, xv), acc);
    }
    s->YP[t * 6 + pl] = acc;
  }
  CLUSTER_BAR();  // peer smem initialized before any DSMEM push

  // kick off first weight chunk
  issue_chunk(s, 0, tid);

  const unsigned peer_h1 = mapa_u32(smem_u32(s->H1rem), (unsigned)(rank ^ 1));
  const float* bufA = rank ? s->H1rem : s->H1loc;  // nodes 0-9
  const float* bufB = rank ? s->H1loc : s->H1rem;  // nodes 10-21

  float osum;
  const int np = (rank == 0 && sub == 2) ? 1 : 2;
  const bool mask = (rank == 1 && sub == 2);
  if (np == 1)
    osum = run_steps<1, false>(s, c, pl0, peer_h1, bufA, bufB, tid);
  else if (mask)
    osum = run_steps<2, true>(s, c, pl0, peer_h1, bufA, bufB, tid);
  else
    osum = run_steps<2, false>(s, c, pl0, peer_h1, bufA, bufB, tid);

  // CTA reduction of clsw-weighted sums
  float v = osum * s->clsw[c];
#pragma unroll
  for (int off = 16; off > 0; off >>= 1)
    v += __shfl_down_sync(0xffffffffu, v, off);
  if ((tid & 31) == 0) s->red[tid >> 5] = v;
  if (tid == 0) s->peer_sum = 0.f;
  __syncthreads();
  float S = 0.f;
  if (tid == 0) {
#pragma unroll
    for (int w = 0; w < 12; w++) S += s->red[w];
    if (rank == 1) stc32(mapa_u32(smem_u32(&s->peer_sum), 0u), S);
  }
  CLUSTER_BAR();
  if (rank == 0 && tid == 0)
    out[b] = (S + s->peer_sum) * (1.0f / (TT * NN)) + clsb[0];
}

// ---------------- launch ----------------
extern "C" void kernel_launch(void* const* d_in, const int* in_sizes, int n_in,
                              void* d_out, int out_size) {
  const float* x = (const float*)d_in[0];
  const int* ei = (const int*)d_in[1];
  const float* ew = (const float*)d_in[2];
  const float* Wz1 = (const float*)d_in[3];
  const float* bz1 = (const float*)d_in[4];
  const float* lzw1 = (const float*)d_in[5];
  const float* lzb1 = (const float*)d_in[6];
  const float* Wr1 = (const float*)d_in[7];
  const float* br1 = (const float*)d_in[8];
  const float* lrw1 = (const float*)d_in[9];
  const float* lrb1 = (const float*)d_in[10];
  const float* Wh1 = (const float*)d_in[11];
  const float* bh1 = (const float*)d_in[12];
  const float* lhw1 = (const float*)d_in[13];
  const float* lhb1 = (const float*)d_in[14];
  const float* Wz2 = (const float*)d_in[15];
  const float* bz2 = (const float*)d_in[16];
  const float* lzw2 = (const float*)d_in[17];
  const float* lzb2 = (const float*)d_in[18];
  const float* Wr2 = (const float*)d_in[19];
  const float* br2 = (const float*)d_in[20];
  const float* lrw2 = (const float*)d_in[21];
  const float* lrb2 = (const float*)d_in[22];
  const float* Wh2 = (const float*)d_in[23];
  const float* bh2 = (const float*)d_in[24];
  const float* lhw2 = (const float*)d_in[25];
  const float* lhb2 = (const float*)d_in[26];
  const float* clsw = (const float*)d_in[27];
  const float* clsb = (const float*)d_in[28];
  int E = in_sizes[1] / 2;

  prep_A_kernel<<<1, 32>>>(ei, ew, E);
  prep_W_kernel<<<128, 256>>>(Wz1, bz1, lzw1, lzb1, Wr1, br1, lrw1, lrb1, Wh1,
                              bh1, lhw1, lhb1, Wz2, bz2, lzw2, lzb2, Wr2, br2,
                              lrw2, lrb2, Wh2, bh2, lhw2, lhb2);

  cudaFuncSetAttribute(tgcn_main, cudaFuncAttributeMaxDynamicSharedMemorySize,
                       (int)sizeof(SM));
  tgcn_main<<<2 * BB, THREADS, sizeof(SM)>>>(x, clsw, clsb, (float*)d_out);
}